// round 2
// baseline (speedup 1.0000x reference)
#include <cuda_runtime.h>
#include <cuda_bf16.h>
#include <cstdint>

#define BB 64
#define DD 2048
#define NN 16384
#define TEMP_F 0.05f
#define NT 64          // n-tile per block
#define KC 32          // k chunk
#define GRID_MAIN (NN / NT)   // 256 blocks

// ---------------- device scratch (no allocations allowed) ----------------
__device__ float g_scale[BB];
__device__ float g_xT[DD * BB];          // transposed, pre-scaled inputs: xT[k][b]
__device__ float g_p1[GRID_MAIN * BB];   // sum exp(logit)
__device__ float g_p2[GRID_MAIN * BB];   // sum exp(t)*logit
__device__ float g_p3[GRID_MAIN * BB];   // sum exp(t)

// ---------------- f32x2 helpers (Blackwell packed dual-fp32) ----------------
__device__ __forceinline__ unsigned long long fma2(unsigned long long a,
                                                   unsigned long long b,
                                                   unsigned long long c) {
    unsigned long long d;
    asm("fma.rn.f32x2 %0, %1, %2, %3;" : "=l"(d) : "l"(a), "l"(b), "l"(c));
    return d;
}
__device__ __forceinline__ unsigned long long pack2(float x) {
    unsigned long long d;
    asm("mov.b64 %0, {%1, %1};" : "=l"(d) : "f"(x));
    return d;
}
__device__ __forceinline__ void unpack2(unsigned long long v, float& lo, float& hi) {
    asm("mov.b64 {%0, %1}, %2;" : "=f"(lo), "=f"(hi) : "l"(v));
}

// ---------------- K1: per-sample inverse norm * 1/TEMP ----------------
__global__ void k_norm(const float* __restrict__ inp) {
    int b = blockIdx.x;
    int t = threadIdx.x;
    float ss = 0.0f;
    const float* row = inp + (size_t)b * DD;
#pragma unroll
    for (int i = 0; i < DD / 256; ++i) {
        float v = row[t + 256 * i];
        ss += v * v;
    }
#pragma unroll
    for (int o = 16; o > 0; o >>= 1) ss += __shfl_xor_sync(0xffffffffu, ss, o);
    __shared__ float w[8];
    if ((t & 31) == 0) w[t >> 5] = ss;
    __syncthreads();
    if (t == 0) {
        float s = 0.0f;
#pragma unroll
        for (int i = 0; i < 8; ++i) s += w[i];
        g_scale[b] = 1.0f / (sqrtf(s) * TEMP_F);
    }
}

// ---------------- K2: transpose + fold scale: xT[k][b] = x[b][k]*scale[b] ----------------
__global__ void k_transpose(const float* __restrict__ inp) {
    int idx = blockIdx.x * blockDim.x + threadIdx.x;   // 0 .. 131071
    int k = idx >> 6;
    int b = idx & 63;
    g_xT[idx] = inp[(size_t)b * DD + k] * g_scale[b];
}

// ---------------- K3: fused GEMM (f32x2) + exp epilogue + per-block partials ----------------
__global__ __launch_bounds__(256) void k_main(const float* __restrict__ targets,
                                              const float* __restrict__ feats) {
    __shared__ __align__(16) char smem_raw[17408];
    float* xs = (float*)smem_raw;                    // [KC][64]      (8192 B)
    float* fs = (float*)(smem_raw + 8192);           // [64][36]      (9216 B)

    const int t  = threadIdx.x;
    const int tx = t & 15;          // b-group: b = 4*tx + i
    const int ty = t >> 4;          // n-group: n = n0 + 4*ty + j
    const int n0 = blockIdx.x * NT;
    const int tx4 = tx * 4;
    const int ty4 = ty * 4;

    unsigned long long acc[4][2];
#pragma unroll
    for (int j = 0; j < 4; ++j) { acc[j][0] = 0ull; acc[j][1] = 0ull; }

    // register staging for the single-buffered pipeline
    float4 xr[2], fr[2];

    // fill-index precompute (2 chunks of 256 threads each for 512 float4 per tile)
    // xs chunk i: idx = t + 256*i : k = idx>>4, g = idx&15
    // fs chunk i: idx = t + 256*i : row = idx>>3, k4 = idx&7
    auto load_regs = [&](int kt) {
#pragma unroll
        for (int i = 0; i < 2; ++i) {
            int idx = t + 256 * i;
            int k = idx >> 4, g = idx & 15;
            xr[i] = *reinterpret_cast<const float4*>(&g_xT[(size_t)(kt * KC + k) * 64 + 4 * g]);
            int row = idx >> 3, k4 = idx & 7;
            fr[i] = *reinterpret_cast<const float4*>(
                &feats[(size_t)(n0 + row) * DD + kt * KC + 4 * k4]);
        }
    };

    load_regs(0);

    for (int kt = 0; kt < DD / KC; ++kt) {
        __syncthreads();   // previous compute finished reading tiles
#pragma unroll
        for (int i = 0; i < 2; ++i) {
            int idx = t + 256 * i;
            int k = idx >> 4, g = idx & 15;
            *reinterpret_cast<float4*>(&xs[k * 64 + 4 * g]) = xr[i];
            int row = idx >> 3, k4 = idx & 7;
            *reinterpret_cast<float4*>(&fs[row * 36 + 4 * k4]) = fr[i];
        }
        __syncthreads();

        if (kt < DD / KC - 1) load_regs(kt + 1);   // LDGs overlap compute below

#pragma unroll
        for (int k = 0; k < KC; ++k) {
            ulonglong2 xv = *reinterpret_cast<const ulonglong2*>(&xs[k * 64 + tx4]);
#pragma unroll
            for (int j = 0; j < 4; ++j) {
                unsigned long long fp = pack2(fs[(ty4 + j) * 36 + k]);
                acc[j][0] = fma2(xv.x, fp, acc[j][0]);
                acc[j][1] = fma2(xv.y, fp, acc[j][1]);
            }
        }
    }

    // -------- epilogue: logits are in acc (scale already folded into xT) --------
    float s1[4], s2[4], zz[4];
#pragma unroll
    for (int i = 0; i < 4; ++i) { s1[i] = 0.0f; s2[i] = 0.0f; zz[i] = 0.0f; }

#pragma unroll
    for (int i = 0; i < 4; ++i) {
        int b = tx4 + i;
        float4 tq = *reinterpret_cast<const float4*>(&targets[(size_t)b * NN + n0 + ty4]);
        float tv[4] = {tq.x, tq.y, tq.z, tq.w};
#pragma unroll
        for (int j = 0; j < 4; ++j) {
            float lo, hi;
            unpack2(acc[j][i >> 1], lo, hi);
            float l  = (i & 1) ? hi : lo;
            float e1 = __expf(l);
            float et = __expf(tv[j]);
            s1[i] += e1;
            s2[i] += et * l;
            zz[i] += et;
        }
    }

    // -------- deterministic block reduction (reuse smem) --------
    __syncthreads();   // everyone done with xs/fs
    float* r1 = (float*)smem_raw;                 // [16][64]
    float* r2 = (float*)(smem_raw + 4096);
    float* r3 = (float*)(smem_raw + 8192);
#pragma unroll
    for (int i = 0; i < 4; ++i) {
        r1[ty * 64 + tx4 + i] = s1[i];
        r2[ty * 64 + tx4 + i] = s2[i];
        r3[ty * 64 + tx4 + i] = zz[i];
    }
    __syncthreads();
    if (t < BB) {
        float a1 = 0.0f, a2 = 0.0f, a3 = 0.0f;
#pragma unroll
        for (int y = 0; y < 16; ++y) {
            a1 += r1[y * 64 + t];
            a2 += r2[y * 64 + t];
            a3 += r3[y * 64 + t];
        }
        g_p1[blockIdx.x * BB + t] = a1;
        g_p2[blockIdx.x * BB + t] = a2;
        g_p3[blockIdx.x * BB + t] = a3;
    }
}

// ---------------- K4: final reduction, loss ----------------
__global__ void k_final(float* __restrict__ out) {
    int t = threadIdx.x;   // 64 threads, t == b
    double s1 = 0.0, s2 = 0.0, z = 0.0;
    for (int blk = 0; blk < GRID_MAIN; ++blk) {
        s1 += (double)g_p1[blk * BB + t];
        s2 += (double)g_p2[blk * BB + t];
        z  += (double)g_p3[blk * BB + t];
    }
    double lb = log(s1) - s2 / z;
    __shared__ double red[BB];
    red[t] = lb;
    __syncthreads();
#pragma unroll
    for (int o = 32; o > 0; o >>= 1) {
        if (t < o) red[t] += red[t + o];
        __syncthreads();
    }
    if (t == 0) out[0] = (float)(red[0] / (double)BB);
}

// ---------------- launch ----------------
extern "C" void kernel_launch(void* const* d_in, const int* in_sizes, int n_in,
                              void* d_out, int out_size) {
    const float* inputs   = (const float*)d_in[0];   // [64][2048]
    const float* targets  = (const float*)d_in[1];   // [64][16384]
    // d_in[2] = cid (unused by the loss)
    const float* features = (const float*)d_in[3];   // [16384][2048]
    float* out = (float*)d_out;

    k_norm<<<BB, 256>>>(inputs);
    k_transpose<<<(DD * BB) / 256, 256>>>(inputs);
    k_main<<<GRID_MAIN, 256>>>(targets, features);
    k_final<<<1, BB>>>(out);
}

// round 5
// speedup vs baseline: 3.0821x; 3.0821x over previous
#include <cuda_runtime.h>
#include <cuda_bf16.h>
#include <cstdint>

#define BB 64
#define DD 2048
#define NN 16384
#define TEMP_F 0.05f
#define MT 128              // feature rows per CTA
#define KC 64               // k per chunk
#define NCH (DD / KC)       // 32
#define GRID (NN / MT)      // 128
#define ASTRIDE 144         // bytes per A/B smem row (64 bf16 + 8 pad)
#define SMEM_DYN 36864

// ---------------- device scratch ----------------
__device__ __nv_bfloat16 g_xB[BB * DD];   // normalized, temp-scaled inputs (bf16)
__device__ float g_p1[GRID * BB];
__device__ float g_p2[GRID * BB];
__device__ float g_p3[GRID * BB];
__device__ double g_lb[BB];

__device__ __forceinline__ uint32_t pack_bf16(float a, float b) {
    __nv_bfloat162 h = __floats2bfloat162_rn(a, b);
    return *reinterpret_cast<uint32_t*>(&h);
}

__device__ __forceinline__ void mma_bf16(float* d, uint32_t a0, uint32_t a1,
                                         uint32_t a2, uint32_t a3,
                                         uint32_t b0, uint32_t b1) {
    asm volatile(
        "mma.sync.aligned.m16n8k16.row.col.f32.bf16.bf16.f32 "
        "{%0,%1,%2,%3}, {%4,%5,%6,%7}, {%8,%9}, {%0,%1,%2,%3};"
        : "+f"(d[0]), "+f"(d[1]), "+f"(d[2]), "+f"(d[3])
        : "r"(a0), "r"(a1), "r"(a2), "r"(a3), "r"(b0), "r"(b1));
}

// ---------------- K1: norm + fold 1/TEMP + bf16 convert ----------------
__global__ void k_prep(const float* __restrict__ inp) {
    int b = blockIdx.x, t = threadIdx.x;
    float v[8], ss = 0.0f;
#pragma unroll
    for (int i = 0; i < 8; ++i) { v[i] = inp[(size_t)b * DD + t + 256 * i]; ss += v[i] * v[i]; }
#pragma unroll
    for (int o = 16; o > 0; o >>= 1) ss += __shfl_xor_sync(0xffffffffu, ss, o);
    __shared__ float w[8]; __shared__ float sc;
    if ((t & 31) == 0) w[t >> 5] = ss;
    __syncthreads();
    if (t == 0) {
        float s = 0.0f;
#pragma unroll
        for (int i = 0; i < 8; ++i) s += w[i];
        sc = 1.0f / (sqrtf(s) * TEMP_F);
    }
    __syncthreads();
    float s = sc;
#pragma unroll
    for (int i = 0; i < 8; ++i) g_xB[(size_t)b * DD + t + 256 * i] = __float2bfloat16(v[i] * s);
}

// ---------------- K2: HMMA GEMM + fused soft-CE epilogue ----------------
__global__ __launch_bounds__(256, 1) void k_main(const float* __restrict__ tg,
                                                 const float* __restrict__ feats) {
    extern __shared__ __align__(16) char dyn[];
    char* As = dyn;                 // [128][ASTRIDE] bytes (bf16, 64 k + pad)
    char* Bs = dyn + MT * ASTRIDE;  // [64][ASTRIDE]

    const int t = threadIdx.x;
    const int w = t >> 5, l = t & 31;
    const int g = l >> 2, u = l & 3;
    const int n0 = blockIdx.x * MT;

    float acc[8][4];
#pragma unroll
    for (int j = 0; j < 8; ++j)
#pragma unroll
        for (int i = 0; i < 4; ++i) acc[j][i] = 0.0f;

    float4 aA[8], nA[8];
    uint2  aB[4], nB[4];
    auto ldc = [&](int cc, float4* A, uint2* Bv) {
#pragma unroll
        for (int i = 0; i < 8; ++i) {
            int f4 = t + 256 * i, row = f4 >> 4, c4 = f4 & 15;
            A[i] = *reinterpret_cast<const float4*>(feats + (size_t)(n0 + row) * DD + cc * KC + c4 * 4);
        }
#pragma unroll
        for (int i = 0; i < 4; ++i) {
            int idx = t + 256 * i, row = idx >> 4, uu = idx & 15;
            Bv[i] = *reinterpret_cast<const uint2*>(g_xB + (size_t)row * DD + cc * KC + uu * 4);
        }
    };

    ldc(0, aA, aB);
    const uint32_t a_base = (16 * w + g) * ASTRIDE + 4 * u;
    const uint32_t b_base = g * ASTRIDE + 4 * u;

    for (int c = 0; c < NCH; ++c) {
        // store staged chunk to smem (bf16)
#pragma unroll
        for (int i = 0; i < 8; ++i) {
            int f4 = t + 256 * i, row = f4 >> 4, c4 = f4 & 15;
            uint2 v; v.x = pack_bf16(aA[i].x, aA[i].y); v.y = pack_bf16(aA[i].z, aA[i].w);
            *reinterpret_cast<uint2*>(As + row * ASTRIDE + c4 * 8) = v;
        }
#pragma unroll
        for (int i = 0; i < 4; ++i) {
            int idx = t + 256 * i, row = idx >> 4, uu = idx & 15;
            *reinterpret_cast<uint2*>(Bs + row * ASTRIDE + uu * 8) = aB[i];
        }
        __syncthreads();

        if (c + 1 < NCH) ldc(c + 1, nA, nB);   // LDGs in flight during mma loop

#pragma unroll
        for (int kt = 0; kt < 4; ++kt) {
            uint32_t a0 = *reinterpret_cast<const uint32_t*>(As + a_base + 32 * kt);
            uint32_t a1 = *reinterpret_cast<const uint32_t*>(As + a_base + 32 * kt + 8 * ASTRIDE);
            uint32_t a2 = *reinterpret_cast<const uint32_t*>(As + a_base + 32 * kt + 16);
            uint32_t a3 = *reinterpret_cast<const uint32_t*>(As + a_base + 32 * kt + 8 * ASTRIDE + 16);
#pragma unroll
            for (int j = 0; j < 8; ++j) {
                uint32_t b0 = *reinterpret_cast<const uint32_t*>(Bs + b_base + j * 8 * ASTRIDE + 32 * kt);
                uint32_t b1 = *reinterpret_cast<const uint32_t*>(Bs + b_base + j * 8 * ASTRIDE + 32 * kt + 16);
                mma_bf16(acc[j], a0, a1, a2, a3, b0, b1);
            }
        }
        __syncthreads();   // all warps done reading tile before next STS

#pragma unroll
        for (int i = 0; i < 8; ++i) aA[i] = nA[i];
#pragma unroll
        for (int i = 0; i < 4; ++i) aB[i] = nB[i];
    }

    // ---- epilogue: logits -> smem L[128][66], fused per-batch partial sums ----
    float* L = (float*)dyn;                       // 128*66*4 = 33792 B
    float* r1 = (float*)(dyn + 33792);            // [4][64]
    float* r2 = r1 + 256;
    float* r3 = r2 + 256;

    {
        int row0 = 16 * w + g;
#pragma unroll
        for (int j = 0; j < 8; ++j) {
            int col = 8 * j + 2 * u;
            *reinterpret_cast<float2*>(&L[row0 * 66 + col])       = make_float2(acc[j][0], acc[j][1]);
            *reinterpret_cast<float2*>(&L[(row0 + 8) * 66 + col]) = make_float2(acc[j][2], acc[j][3]);
        }
    }
    __syncthreads();

    {
        int cb = t & 63, q = t >> 6;     // column (batch), row-quarter
        float s1 = 0.0f, s2 = 0.0f, s3 = 0.0f;
        const float* tgp = tg + (size_t)cb * NN + n0 + 32 * q;
#pragma unroll 4
        for (int i = 0; i < 32; ++i) {
            float lv = L[(32 * q + i) * 66 + cb];
            s1 += __expf(lv);
            float tv = tgp[i];
            float et = (tv != 0.0f) ? __expf(tv) : 1.0f;   // exact: e^0 == 1
            s3 += et;
            s2 += et * lv;
        }
        r1[t] = s1; r2[t] = s2; r3[t] = s3;
    }
    __syncthreads();
    if (t < BB) {
        float a1 = 0.0f, a2 = 0.0f, a3 = 0.0f;
#pragma unroll
        for (int q = 0; q < 4; ++q) {
            a1 += r1[q * 64 + t]; a2 += r2[q * 64 + t]; a3 += r3[q * 64 + t];
        }
        g_p1[blockIdx.x * BB + t] = a1;
        g_p2[blockIdx.x * BB + t] = a2;
        g_p3[blockIdx.x * BB + t] = a3;
    }
}

// ---------------- K3: per-b reduction over 128 CTAs ----------------
__global__ void k_red(void) {
    int b = blockIdx.x, c = threadIdx.x;   // 128 threads
    __shared__ double s1[128], s2[128], s3[128];
    s1[c] = (double)g_p1[c * BB + b];
    s2[c] = (double)g_p2[c * BB + b];
    s3[c] = (double)g_p3[c * BB + b];
    __syncthreads();
#pragma unroll
    for (int o = 64; o > 0; o >>= 1) {
        if (c < o) { s1[c] += s1[c + o]; s2[c] += s2[c + o]; s3[c] += s3[c + o]; }
        __syncthreads();
    }
    if (c == 0) g_lb[b] = log(s1[0]) - s2[0] / s3[0];
}

// ---------------- K4: final scalar ----------------
__global__ void k_fin(float* __restrict__ out) {
    int t = threadIdx.x;   // 64
    __shared__ double sd[BB];
    sd[t] = g_lb[t];
    __syncthreads();
#pragma unroll
    for (int o = 32; o > 0; o >>= 1) {
        if (t < o) sd[t] += sd[t + o];
        __syncthreads();
    }
    if (t == 0) out[0] = (float)(sd[0] / (double)BB);
}

// ---------------- launch ----------------
extern "C" void kernel_launch(void* const* d_in, const int* in_sizes, int n_in,
                              void* d_out, int out_size) {
    const float* inputs   = (const float*)d_in[0];
    const float* targets  = (const float*)d_in[1];
    const float* features = (const float*)d_in[3];
    float* out = (float*)d_out;

    k_prep<<<BB, 256>>>(inputs);
    k_main<<<GRID, 256, SMEM_DYN>>>(targets, features);
    k_red<<<BB, 128>>>();
    k_fin<<<1, BB>>>(out);
}